// round 12
// baseline (speedup 1.0000x reference)
#include <cuda_runtime.h>

#define EPSF 1e-6f
#define FULLM 0xffffffffu

constexpr int cV = 128, cK = 32, cC = 256;
constexpr int cL = 4, cN = 4096, cF = 16;
constexpr int cE = 8192, cB = 512;
constexpr int cB4 = cB / 4;            // 128 float4 groups per row
constexpr int NT   = 512;
constexpr int BPSM = 2;                // blocks/SM via launch_bounds (64-reg budget)
constexpr int GRID = 148 * BPSM;       // 296 persistent blocks
constexpr int NWARP = GRID * NT / 32;  // 4736 warps
constexpr float LN2F = 0.69314718055994530942f;

// ---- scratch (static __device__ per allocation rules) ----
__device__ __align__(16) float d_lwlin[cV * cK * cC];  // 4 MB linear mantissas (rowmax=1)
__device__ __align__(16) float d_eIn[cV * cK];         // input row scales (log2)
__device__ __align__(16) int4  d_fw[cL * cN * cF];     // 4 MB {c0*cB4, c1*cB4, W, 0}
__device__ __align__(16) float d_R[cN];                // linear root weights
__device__ __align__(16) float d_e0[cN * 4];           // layer-0 (row,quarter) scales
__device__ __align__(16) float d_eA[cN * 4];           // scale ping
__device__ __align__(16) float d_eB[cN * 4];           // scale pong
__device__ __align__(16) int   d_xT[cV * cB];          // transposed inputs
__device__ __align__(16) float d_nmA[cN * cB];         // 8 MB
__device__ __align__(16) float d_nmB[cN * cB];         // 8 MB

// ---- grid barrier state ----
__device__ unsigned d_bar_count = 0;
__device__ volatile unsigned d_bar_gen = 0;

// ---- single-instruction MUFU ops ----
__device__ __forceinline__ float ex2(float x) {
    float y; asm("ex2.approx.ftz.f32 %0, %1;" : "=f"(y) : "f"(x)); return y;
}
__device__ __forceinline__ float lg2(float x) {
    float y; asm("lg2.approx.ftz.f32 %0, %1;" : "=f"(y) : "f"(x)); return y;
}
__device__ __forceinline__ float rcp(float x) {
    float y; asm("rcp.approx.ftz.f32 %0, %1;" : "=f"(y) : "f"(x)); return y;
}

// ==================================================================
// PREP: linear mantissa input table + row scales, fused tables
// {c0,c1,W linear}, linear root weights, input transpose.
// ==================================================================
__global__ void __launch_bounds__(256) k_prep(const float* __restrict__ ip,
                                              const float* __restrict__ sp,
                                              const float* __restrict__ rp,
                                              const int*   __restrict__ inputs,
                                              const int*   __restrict__ sci,
                                              const int*   __restrict__ pc) {
    int b = blockIdx.x;
    if (b < 512) {
        // --- input rows: linear mantissas (rowmax=1) + log2 scale ---
        int w    = b * 8 + (threadIdx.x >> 5);
        int lane = threadIdx.x & 31;
        const float* row = ip + w * cC;
        float v[8];
        float tot = 0.f, mx = 0.f;
#pragma unroll
        for (int i = 0; i < 8; i++) {
            v[i] = row[lane + i * 32] + EPSF;
            tot += v[i];
            mx = fmaxf(mx, v[i]);
        }
#pragma unroll
        for (int o = 16; o; o >>= 1) {
            tot += __shfl_xor_sync(FULLM, tot, o);
            mx = fmaxf(mx, __shfl_xor_sync(FULLM, mx, o));
        }
        float inv = 1.f / mx;
#pragma unroll
        for (int i = 0; i < 8; i++) d_lwlin[w * cC + lane + i * 32] = v[i] * inv;
        if (lane == 0) d_eIn[w] = lg2(mx / tot);   // true = mant * 2^e
    } else if (b < 576) {
        // --- fused tables: one thread per (l,n): {c0*cB4, c1*cB4, W} ---
        int r = (b - 512) * 256 + threadIdx.x;
        int l = r / cN;
        const float* spr  = sp  + r * cF;
        const int*   scir = sci + r * cF;
        const int2*  pcl  = reinterpret_cast<const int2*>(pc) + l * cE;
        float w[cF];
        float tot = 0.f;
#pragma unroll
        for (int f = 0; f < cF; f++) { w[f] = spr[f] + EPSF; tot += w[f]; }
        float inv = 1.f / tot;
        int4* dst = d_fw + r * cF;
#pragma unroll
        for (int f = 0; f < cF; f++) {
            int2 c = pcl[scir[f]];
            dst[f] = make_int4(c.x * cB4, c.y * cB4, __float_as_int(w[f] * inv), 0);
        }
    } else if (b == 576) {
        // --- root params: linear normalize over N=4096 ---
        __shared__ float red[256];
        int t = threadIdx.x;
        float v[16];
        float s = 0.f;
#pragma unroll
        for (int i = 0; i < 16; i++) {
            v[i] = rp[t + i * 256] + EPSF;
            s += v[i];
        }
        red[t] = s;
        __syncthreads();
        for (int o = 128; o; o >>= 1) {
            if (t < o) red[t] += red[t + o];
            __syncthreads();
        }
        float inv = 1.f / red[0];
#pragma unroll
        for (int i = 0; i < 16; i++) d_R[t + i * 256] = v[i] * inv;
    } else {
        // --- transpose inputs (B,V) -> xT (V,B) ---
        int id = (b - 577) * 256 + threadIdx.x;
        for (int i = id; i < cV * cB; i += 64 * 256) {
            int bb = i >> 7;
            int vv = i & 127;
            d_xT[vv * cB + bb] = inputs[i];
        }
    }
}

// ==================================================================
// grid barrier (all GRID blocks resident).
// ==================================================================
__device__ __forceinline__ void grid_barrier() {
    __syncthreads();
    if (threadIdx.x == 0) {
        __threadfence();
        unsigned gen = d_bar_gen;
        unsigned t   = atomicAdd(&d_bar_count, 1u);
        if (t == GRID - 1) {
            d_bar_count = 0;
            __threadfence();
            d_bar_gen = gen + 1;
        } else {
            while (d_bar_gen == gen) { __nanosleep(64); }
        }
        __threadfence();
    }
    __syncthreads();
}

// ==================================================================
// PERSISTENT kernel — LINEAR mantissa layers, per-(row,quarter) scales.
// Task = warp per (n, quarter). coef_f = W_f * 2^(e[c0,q]+e[c1,q]-G);
// acc[b] = sum_f coef_f * a_f[b]*b_f[b]  (pure FMA inner loop).
// Store mant = acc/qmax, e_out = G + lg2(qmax).
// Last layer emits log2 values; root LSE unchanged.
// ==================================================================
__global__ void __launch_bounds__(NT, BPSM) k_persist(float* __restrict__ out) {
    __shared__ float4 s_m[NT];
    __shared__ float4 s_s[NT];
    const int t    = threadIdx.x;
    const int lane = t & 31;
    const int wid  = (blockIdx.x * NT + t) >> 5;   // global warp id

    // ---------- phase 0: input gather (linear mantissas) + layer-0 scales ----------
    {
        const int stride = GRID * NT;
        int gid = blockIdx.x * NT + t;
        for (int i = gid; i < cN * cB; i += stride) {
            int b  = i & (cB - 1);
            int vk = i >> 9;
            int v  = vk >> 5;
            int x  = d_xT[v * cB + b];
            d_nmA[i] = d_lwlin[vk * cC + x];
        }
        if (gid < cN * 4) d_e0[gid] = d_eIn[gid >> 2];   // scale uniform per row
    }
    grid_barrier();

    // ---------- 4 fused linear layers ----------
    float* nm_src = d_nmA;
    float* nm_dst = d_nmB;
    const float* esrc = d_e0;
    for (int l = 0; l < cL; l++) {
        float* edst = (l & 1) ? d_eB : d_eA;
        const int4*   fwl = d_fw + l * cN * cF;
        const float4* nmS = reinterpret_cast<const float4*>(nm_src);

        for (int task = wid; task < cN * 4; task += NWARP) {
            int n = task >> 2;
            int q = task & 3;
            int g = (q << 5) + lane;
            // lane f (mirrored at f+16) owns table entry f
            int4 pm = __ldg(fwl + n * cF + (lane & 15));
            // per-(row,quarter) scale lookup: c*4+q == (c*cB4)>>5 + q
            float g_my = __ldg(esrc + (pm.x >> 5) + q) + __ldg(esrc + (pm.y >> 5) + q);
            float G = g_my;
#pragma unroll
            for (int o = 1; o < 16; o <<= 1)
                G = fmaxf(G, __shfl_xor_sync(FULLM, G, o));
            float coef_my = __int_as_float(pm.z) * ex2(g_my - G);

            // depth-2 pipelined gathers
            float4 aA = nmS[__shfl_sync(FULLM, pm.x, 0) + g];
            float4 bA = nmS[__shfl_sync(FULLM, pm.y, 0) + g];
            float4 aB = nmS[__shfl_sync(FULLM, pm.x, 1) + g];
            float4 bB = nmS[__shfl_sync(FULLM, pm.y, 1) + g];

            float4 acc = make_float4(0.f, 0.f, 0.f, 0.f);
#pragma unroll
            for (int f = 0; f < cF; f++) {
                float cf = __shfl_sync(FULLM, coef_my, f);
                float4 a = aA, b = bA;
                aA = aB; bA = bB;
                if (f + 2 < cF) {
                    aB = nmS[__shfl_sync(FULLM, pm.x, f + 2) + g];
                    bB = nmS[__shfl_sync(FULLM, pm.y, f + 2) + g];
                }
                acc.x += cf * (a.x * b.x);
                acc.y += cf * (a.y * b.y);
                acc.z += cf * (a.z * b.z);
                acc.w += cf * (a.w * b.w);
            }

            float4* dst = reinterpret_cast<float4*>(nm_dst) + n * cB4 + g;
            if (l < cL - 1) {
                // quarter renormalize: qmax -> 1, fold into e_out
                float qm = fmaxf(fmaxf(acc.x, acc.y), fmaxf(acc.z, acc.w));
#pragma unroll
                for (int o = 16; o; o >>= 1)
                    qm = fmaxf(qm, __shfl_xor_sync(FULLM, qm, o));
                float ri = rcp(qm);
                float4 w;
                w.x = acc.x * ri; w.y = acc.y * ri;
                w.z = acc.z * ri; w.w = acc.w * ri;
                __stcg(dst, w);
                if (lane == 0) edst[n * 4 + q] = G + lg2(qm);
            } else {
                // final layer: emit log2 values for the root reduction
                float4 w;
                w.x = G + lg2(acc.x); w.y = G + lg2(acc.y);
                w.z = G + lg2(acc.z); w.w = G + lg2(acc.w);
                __stcg(dst, w);
            }
        }
        grid_barrier();

        float* tmp = nm_src; nm_src = nm_dst; nm_dst = tmp;
        esrc = edst;
    }

    // ---------- root: out[b] = ln2 * (m + lg2(sum_n R_n 2^(x_nb - m))) ----------
    if (blockIdx.x < cB4) {
        const int g = blockIdx.x;              // float4 batch group
        const float4* nmp = reinterpret_cast<const float4*>(nm_src);

        float R0 = __ldg(d_R + t);
        float4 m = nmp[t * cB4 + g];
        float4 s = make_float4(R0, R0, R0, R0);
#pragma unroll
        for (int k = 1; k < cN / NT; k++) {
            int   n = t + k * NT;
            float R = __ldg(d_R + n);
            float4 x = nmp[n * cB4 + g];
            s.x += R * ex2(x.x - m.x);
            s.y += R * ex2(x.y - m.y);
            s.z += R * ex2(x.z - m.z);
            s.w += R * ex2(x.w - m.w);
        }
        s_m[t] = m; s_s[t] = s;
        __syncthreads();
        for (int o = NT / 2; o; o >>= 1) {
            if (t < o) {
                float4 m1 = s_m[t], m2 = s_m[t + o];
                float4 s1 = s_s[t], s2 = s_s[t + o];
                float4 mm, ss;
                mm.x = fmaxf(m1.x, m2.x);
                mm.y = fmaxf(m1.y, m2.y);
                mm.z = fmaxf(m1.z, m2.z);
                mm.w = fmaxf(m1.w, m2.w);
                ss.x = s1.x * ex2(m1.x - mm.x) + s2.x * ex2(m2.x - mm.x);
                ss.y = s1.y * ex2(m1.y - mm.y) + s2.y * ex2(m2.y - mm.y);
                ss.z = s1.z * ex2(m1.z - mm.z) + s2.z * ex2(m2.z - mm.z);
                ss.w = s1.w * ex2(m1.w - mm.w) + s2.w * ex2(m2.w - mm.w);
                s_m[t] = mm; s_s[t] = ss;
            }
            __syncthreads();
        }
        if (t == 0) {
            float4 m0 = s_m[0], s0 = s_s[0];
            out[g * 4 + 0] = (m0.x + lg2(s0.x)) * LN2F;
            out[g * 4 + 1] = (m0.y + lg2(s0.y)) * LN2F;
            out[g * 4 + 2] = (m0.z + lg2(s0.z)) * LN2F;
            out[g * 4 + 3] = (m0.w + lg2(s0.w)) * LN2F;
        }
    }
}

// ==================================================================
extern "C" void kernel_launch(void* const* d_in, const int* in_sizes, int n_in,
                              void* d_out, int out_size) {
    const int*   inputs = (const int*)d_in[0];    // (B, V)
    const int*   pc     = (const int*)d_in[1];    // (L, E, 2)
    const int*   sci    = (const int*)d_in[2];    // (L, N, F)
    const float* ip     = (const float*)d_in[3];  // (V, K, C)
    const float* sp     = (const float*)d_in[4];  // (L, N, F)
    const float* rp     = (const float*)d_in[5];  // (N,)
    float* out = (float*)d_out;                   // (B,)

    k_prep<<<641, 256>>>(ip, sp, rp, inputs, sci, pc);
    k_persist<<<GRID, NT>>>(out);
}

// round 13
// speedup vs baseline: 1.4243x; 1.4243x over previous
#include <cuda_runtime.h>
#include <cuda_fp16.h>

#define EPSF 1e-6f
#define FULLM 0xffffffffu

constexpr int cV = 128, cK = 32, cC = 256;
constexpr int cL = 4, cN = 4096, cF = 16;
constexpr int cE = 8192, cB = 512;
constexpr int cB2h = cB / 2;           // 256 half2 per row
constexpr int cB4 = cB / 4;            // 128 float4 groups per fp32 row
constexpr int cBu4 = cB / 8;           // 64 uint4 (16B) groups per half row
constexpr int NT   = 512;
constexpr int BPSM = 2;
constexpr int GRID = 148 * BPSM;       // 296 persistent blocks
constexpr int NWARP = GRID * NT / 32;  // 4736 warps
constexpr float LN2F = 0.69314718055994530942f;

// ---- scratch (static __device__ per allocation rules) ----
__device__ __align__(16) __half d_lwlin[cV * cK * cC]; // 2 MB linear mantissas (rowmax=1)
__device__ __align__(16) float  d_eIn[cV * cK];        // input row scales (log2)
__device__ __align__(16) int4   d_fw[cL * cN * cF];    // 4 MB {c0*cBu4, c1*cBu4, W, 0}
__device__ __align__(16) float  d_R[cN];               // linear root weights
__device__ __align__(16) float  d_e0[cN * 2];          // layer-0 (row,half) scales
__device__ __align__(16) float  d_eA[cN * 2];          // scale ping
__device__ __align__(16) float  d_eB[cN * 2];          // scale pong
__device__ __align__(16) int    d_xT[cV * cB];         // transposed inputs
__device__ __align__(16) __half d_nmA[cN * cB];        // 4 MB mantissas ping
__device__ __align__(16) __half d_nmB[cN * cB];        // 4 MB mantissas pong
__device__ __align__(16) float  d_fin[cN * cB];        // 8 MB final log2 values

// ---- grid barrier state ----
__device__ unsigned d_bar_count = 0;
__device__ volatile unsigned d_bar_gen = 0;

// ---- single-instruction MUFU ops ----
__device__ __forceinline__ float ex2(float x) {
    float y; asm("ex2.approx.ftz.f32 %0, %1;" : "=f"(y) : "f"(x)); return y;
}
__device__ __forceinline__ float lg2(float x) {
    float y; asm("lg2.approx.ftz.f32 %0, %1;" : "=f"(y) : "f"(x)); return y;
}
__device__ __forceinline__ float rcp(float x) {
    float y; asm("rcp.approx.ftz.f32 %0, %1;" : "=f"(y) : "f"(x)); return y;
}
__device__ __forceinline__ __half2 u2h2(unsigned u) {
    __half2 h; *reinterpret_cast<unsigned*>(&h) = u; return h;
}
__device__ __forceinline__ unsigned h2u(__half2 h) {
    return *reinterpret_cast<unsigned*>(&h);
}

// ==================================================================
// PREP: fp16 linear mantissa input table + row scales, fused tables
// {c0,c1,W linear}, linear root weights, input transpose.
// ==================================================================
__global__ void __launch_bounds__(256) k_prep(const float* __restrict__ ip,
                                              const float* __restrict__ sp,
                                              const float* __restrict__ rp,
                                              const int*   __restrict__ inputs,
                                              const int*   __restrict__ sci,
                                              const int*   __restrict__ pc) {
    int b = blockIdx.x;
    if (b < 512) {
        // --- input rows: linear mantissas (rowmax=1) + log2 scale ---
        int w    = b * 8 + (threadIdx.x >> 5);
        int lane = threadIdx.x & 31;
        const float* row = ip + w * cC;
        float v[8];
        float tot = 0.f, mx = 0.f;
#pragma unroll
        for (int i = 0; i < 8; i++) {
            v[i] = row[lane + i * 32] + EPSF;
            tot += v[i];
            mx = fmaxf(mx, v[i]);
        }
#pragma unroll
        for (int o = 16; o; o >>= 1) {
            tot += __shfl_xor_sync(FULLM, tot, o);
            mx = fmaxf(mx, __shfl_xor_sync(FULLM, mx, o));
        }
        float inv = 1.f / mx;
#pragma unroll
        for (int i = 0; i < 8; i++)
            d_lwlin[w * cC + lane + i * 32] = __float2half_rn(v[i] * inv);
        if (lane == 0) d_eIn[w] = lg2(mx / tot);    // true = mant * 2^e
    } else if (b < 576) {
        // --- fused tables: one thread per (l,n): {c0*cBu4, c1*cBu4, W} ---
        int r = (b - 512) * 256 + threadIdx.x;
        int l = r / cN;
        const float* spr  = sp  + r * cF;
        const int*   scir = sci + r * cF;
        const int2*  pcl  = reinterpret_cast<const int2*>(pc) + l * cE;
        float w[cF];
        float tot = 0.f;
#pragma unroll
        for (int f = 0; f < cF; f++) { w[f] = spr[f] + EPSF; tot += w[f]; }
        float inv = 1.f / tot;
        int4* dst = d_fw + r * cF;
#pragma unroll
        for (int f = 0; f < cF; f++) {
            int2 c = pcl[scir[f]];
            dst[f] = make_int4(c.x * cBu4, c.y * cBu4, __float_as_int(w[f] * inv), 0);
        }
    } else if (b == 576) {
        // --- root params: linear normalize over N=4096 ---
        __shared__ float red[256];
        int t = threadIdx.x;
        float v[16];
        float s = 0.f;
#pragma unroll
        for (int i = 0; i < 16; i++) {
            v[i] = rp[t + i * 256] + EPSF;
            s += v[i];
        }
        red[t] = s;
        __syncthreads();
        for (int o = 128; o; o >>= 1) {
            if (t < o) red[t] += red[t + o];
            __syncthreads();
        }
        float inv = 1.f / red[0];
#pragma unroll
        for (int i = 0; i < 16; i++) d_R[t + i * 256] = v[i] * inv;
    } else {
        // --- transpose inputs (B,V) -> xT (V,B) ---
        int id = (b - 577) * 256 + threadIdx.x;
        for (int i = id; i < cV * cB; i += 64 * 256) {
            int bb = i >> 7;
            int vv = i & 127;
            d_xT[vv * cB + bb] = inputs[i];
        }
    }
}

// ==================================================================
// grid barrier (all GRID blocks resident).
// ==================================================================
__device__ __forceinline__ void grid_barrier() {
    __syncthreads();
    if (threadIdx.x == 0) {
        __threadfence();
        unsigned gen = d_bar_gen;
        unsigned t   = atomicAdd(&d_bar_count, 1u);
        if (t == GRID - 1) {
            d_bar_count = 0;
            __threadfence();
            d_bar_gen = gen + 1;
        } else {
            while (d_bar_gen == gen) { __nanosleep(64); }
        }
        __threadfence();
    }
    __syncthreads();
}

// ==================================================================
// PERSISTENT kernel — fp16 linear mantissa layers, per-(row,half) scales.
// Task = warp per (n, row-half: 256 batch elems, 1 uint4/lane).
// coef_f = W_f * 2^(e[c0,h]+e[c1,h]-G); products in half2, acc in fp32.
// Store mant = acc/qmax (half2), e_out = G + lg2(qmax).
// Last layer emits fp32 log2 into d_fin; root LSE unchanged.
// ==================================================================
__global__ void __launch_bounds__(NT, BPSM) k_persist(float* __restrict__ out) {
    __shared__ float4 s_m[NT];
    __shared__ float4 s_s[NT];
    const int t    = threadIdx.x;
    const int lane = t & 31;
    const int wid  = (blockIdx.x * NT + t) >> 5;   // global warp id

    // ---------- phase 0: input gather (half2 mantissas) + layer-0 scales ----------
    {
        const int stride = GRID * NT;
        int gid = blockIdx.x * NT + t;
        __half2* nmA2 = reinterpret_cast<__half2*>(d_nmA);
        for (int i = gid; i < cN * cB2h; i += stride) {
            int b2 = i & (cB2h - 1);          // half2 index in row
            int vk = i >> 8;                  // row
            int v  = vk >> 5;
            int x0 = d_xT[v * cB + b2 * 2];
            int x1 = d_xT[v * cB + b2 * 2 + 1];
            nmA2[i] = __halves2half2(d_lwlin[vk * cC + x0], d_lwlin[vk * cC + x1]);
        }
        if (gid < cN * 2) d_e0[gid] = d_eIn[gid >> 1];
    }
    grid_barrier();

    // ---------- 4 fused linear layers ----------
    __half* nm_src = d_nmA;
    __half* nm_dst = d_nmB;
    const float* esrc = d_e0;
    for (int l = 0; l < cL; l++) {
        float* edst = (l & 1) ? d_eB : d_eA;
        const int4*  fwl = d_fw + l * cN * cF;
        const uint4* nmS = reinterpret_cast<const uint4*>(nm_src);

        for (int task = wid; task < cN * 2; task += NWARP) {
            int n = task >> 1;
            int h = task & 1;
            int g = (h << 5) + lane;           // uint4 index in row
            // lane f (mirrored at f+16) owns table entry f
            int4 pm = __ldg(fwl + n * cF + (lane & 15));
            // per-(row,half) scale: row = pm.x/cBu4; idx = row*2+h = (pm.x>>5)+h
            float g_my = __ldg(esrc + (pm.x >> 5) + h) + __ldg(esrc + (pm.y >> 5) + h);
            float G = g_my;
#pragma unroll
            for (int o = 1; o < 16; o <<= 1)
                G = fmaxf(G, __shfl_xor_sync(FULLM, G, o));
            float coef_my = __int_as_float(pm.z) * ex2(g_my - G);

            // depth-2 pipelined gathers (16B/lane covers 8 batch elems)
            uint4 aA = nmS[__shfl_sync(FULLM, pm.x, 0) + g];
            uint4 bA = nmS[__shfl_sync(FULLM, pm.y, 0) + g];
            uint4 aB = nmS[__shfl_sync(FULLM, pm.x, 1) + g];
            uint4 bB = nmS[__shfl_sync(FULLM, pm.y, 1) + g];

            float acc[8];
#pragma unroll
            for (int j = 0; j < 8; j++) acc[j] = 0.f;

#pragma unroll
            for (int f = 0; f < cF; f++) {
                float cf = __shfl_sync(FULLM, coef_my, f);
                uint4 a = aA, b = bA;
                aA = aB; bA = bB;
                if (f + 2 < cF) {
                    aB = nmS[__shfl_sync(FULLM, pm.x, f + 2) + g];
                    bB = nmS[__shfl_sync(FULLM, pm.y, f + 2) + g];
                }
                float2 p0 = __half22float2(__hmul2(u2h2(a.x), u2h2(b.x)));
                float2 p1 = __half22float2(__hmul2(u2h2(a.y), u2h2(b.y)));
                float2 p2 = __half22float2(__hmul2(u2h2(a.z), u2h2(b.z)));
                float2 p3 = __half22float2(__hmul2(u2h2(a.w), u2h2(b.w)));
                acc[0] += cf * p0.x; acc[1] += cf * p0.y;
                acc[2] += cf * p1.x; acc[3] += cf * p1.y;
                acc[4] += cf * p2.x; acc[5] += cf * p2.y;
                acc[6] += cf * p3.x; acc[7] += cf * p3.y;
            }

            if (l < cL - 1) {
                // half-row renormalize: qmax -> 1, fold into e_out
                float qm = acc[0];
#pragma unroll
                for (int j = 1; j < 8; j++) qm = fmaxf(qm, acc[j]);
#pragma unroll
                for (int o = 16; o; o >>= 1)
                    qm = fmaxf(qm, __shfl_xor_sync(FULLM, qm, o));
                float ri = rcp(qm);
                uint4 o4;
                o4.x = h2u(__floats2half2_rn(acc[0] * ri, acc[1] * ri));
                o4.y = h2u(__floats2half2_rn(acc[2] * ri, acc[3] * ri));
                o4.z = h2u(__floats2half2_rn(acc[4] * ri, acc[5] * ri));
                o4.w = h2u(__floats2half2_rn(acc[6] * ri, acc[7] * ri));
                __stcg(reinterpret_cast<uint4*>(nm_dst) + n * cBu4 + g, o4);
                if (lane == 0) edst[n * 2 + h] = G + lg2(qm);
            } else {
                // final layer: emit fp32 log2 values for the root reduction
                float4 w0, w1;
                w0.x = G + lg2(acc[0]); w0.y = G + lg2(acc[1]);
                w0.z = G + lg2(acc[2]); w0.w = G + lg2(acc[3]);
                w1.x = G + lg2(acc[4]); w1.y = G + lg2(acc[5]);
                w1.z = G + lg2(acc[6]); w1.w = G + lg2(acc[7]);
                float4* fd = reinterpret_cast<float4*>(d_fin) + n * cB4 + g * 2;
                __stcg(fd, w0);
                __stcg(fd + 1, w1);
            }
        }
        grid_barrier();

        __half* tmp = nm_src; nm_src = nm_dst; nm_dst = tmp;
        esrc = edst;
    }

    // ---------- root: out[b] = ln2 * (m + lg2(sum_n R_n 2^(x_nb - m))) ----------
    if (blockIdx.x < cB4) {
        const int g = blockIdx.x;              // float4 batch group
        const float4* nmp = reinterpret_cast<const float4*>(d_fin);

        float R0 = __ldg(d_R + t);
        float4 m = nmp[t * cB4 + g];
        float4 s = make_float4(R0, R0, R0, R0);
#pragma unroll
        for (int k = 1; k < cN / NT; k++) {
            int   n = t + k * NT;
            float R = __ldg(d_R + n);
            float4 x = nmp[n * cB4 + g];
            s.x += R * ex2(x.x - m.x);
            s.y += R * ex2(x.y - m.y);
            s.z += R * ex2(x.z - m.z);
            s.w += R * ex2(x.w - m.w);
        }
        s_m[t] = m; s_s[t] = s;
        __syncthreads();
        for (int o = NT / 2; o; o >>= 1) {
            if (t < o) {
                float4 m1 = s_m[t], m2 = s_m[t + o];
                float4 s1 = s_s[t], s2 = s_s[t + o];
                float4 mm, ss;
                mm.x = fmaxf(m1.x, m2.x);
                mm.y = fmaxf(m1.y, m2.y);
                mm.z = fmaxf(m1.z, m2.z);
                mm.w = fmaxf(m1.w, m2.w);
                ss.x = s1.x * ex2(m1.x - mm.x) + s2.x * ex2(m2.x - mm.x);
                ss.y = s1.y * ex2(m1.y - mm.y) + s2.y * ex2(m2.y - mm.y);
                ss.z = s1.z * ex2(m1.z - mm.z) + s2.z * ex2(m2.z - mm.z);
                ss.w = s1.w * ex2(m1.w - mm.w) + s2.w * ex2(m2.w - mm.w);
                s_m[t] = mm; s_s[t] = ss;
            }
            __syncthreads();
        }
        if (t == 0) {
            float4 m0 = s_m[0], s0 = s_s[0];
            out[g * 4 + 0] = (m0.x + lg2(s0.x)) * LN2F;
            out[g * 4 + 1] = (m0.y + lg2(s0.y)) * LN2F;
            out[g * 4 + 2] = (m0.z + lg2(s0.z)) * LN2F;
            out[g * 4 + 3] = (m0.w + lg2(s0.w)) * LN2F;
        }
    }
}

// ==================================================================
extern "C" void kernel_launch(void* const* d_in, const int* in_sizes, int n_in,
                              void* d_out, int out_size) {
    const int*   inputs = (const int*)d_in[0];    // (B, V)
    const int*   pc     = (const int*)d_in[1];    // (L, E, 2)
    const int*   sci    = (const int*)d_in[2];    // (L, N, F)
    const float* ip     = (const float*)d_in[3];  // (V, K, C)
    const float* sp     = (const float*)d_in[4];  // (L, N, F)
    const float* rp     = (const float*)d_in[5];  // (N,)
    float* out = (float*)d_out;                   // (B,)

    k_prep<<<641, 256>>>(ip, sp, rp, inputs, sci, pc);
    k_persist<<<GRID, NT>>>(out);
}

// round 14
// speedup vs baseline: 1.4711x; 1.0329x over previous
#include <cuda_runtime.h>
#include <cuda_fp16.h>

#define EPSF 1e-6f
#define FULLM 0xffffffffu

constexpr int cV = 128, cK = 32, cC = 256;
constexpr int cL = 4, cN = 4096, cF = 16;
constexpr int cE = 8192, cB = 512;
constexpr int cB2h = cB / 2;           // 256 half2 per row
constexpr int cB4 = cB / 4;            // 128 float4 groups per fp32 row
constexpr int cBu4 = cB / 8;           // 64 uint4 (16B) groups per half row
constexpr int NT   = 512;
constexpr int BPSM = 2;
constexpr int GRID = 256;              // 8192 sum tasks / 4096 warps = exactly 2
constexpr int NWARP = GRID * NT / 32;  // 4096 warps
constexpr float LN2F = 0.69314718055994530942f;

// ---- scratch (static __device__ per allocation rules) ----
__device__ __align__(16) __half d_lwlin[cV * cK * cC]; // 2 MB linear mantissas (rowmax=1)
__device__ __align__(16) float  d_eIn[cV * cK];        // input row scales (log2)
__device__ __align__(16) int4   d_fw[cL * cN * cF];    // 4 MB {c0*cBu4, c1*cBu4, W, 0}
__device__ __align__(16) float  d_R[cN];               // linear root weights
__device__ __align__(16) float  d_e0[cN * 2];          // layer-0 (row,half) scales
__device__ __align__(16) float  d_eA[cN * 2];          // scale ping
__device__ __align__(16) float  d_eB[cN * 2];          // scale pong
__device__ __align__(16) int    d_xT[cV * cB];         // transposed inputs
__device__ __align__(16) __half d_nmA[cN * cB];        // 4 MB mantissas ping
__device__ __align__(16) __half d_nmB[cN * cB];        // 4 MB mantissas pong
__device__ __align__(16) float  d_fin[cN * cB];        // 8 MB final log2 values

// ---- grid barrier state ----
__device__ unsigned d_bar_count = 0;
__device__ volatile unsigned d_bar_gen = 0;

// ---- single-instruction MUFU ops ----
__device__ __forceinline__ float ex2(float x) {
    float y; asm("ex2.approx.ftz.f32 %0, %1;" : "=f"(y) : "f"(x)); return y;
}
__device__ __forceinline__ float lg2(float x) {
    float y; asm("lg2.approx.ftz.f32 %0, %1;" : "=f"(y) : "f"(x)); return y;
}
__device__ __forceinline__ float rcp(float x) {
    float y; asm("rcp.approx.ftz.f32 %0, %1;" : "=f"(y) : "f"(x)); return y;
}
__device__ __forceinline__ __half2 u2h2(unsigned u) {
    __half2 h; *reinterpret_cast<unsigned*>(&h) = u; return h;
}
__device__ __forceinline__ unsigned h2u(__half2 h) {
    return *reinterpret_cast<unsigned*>(&h);
}

// ==================================================================
// PREP: fp16 linear mantissa input table + row scales, fused tables
// {c0,c1,W linear}, linear root weights, input transpose.
// ==================================================================
__global__ void __launch_bounds__(256) k_prep(const float* __restrict__ ip,
                                              const float* __restrict__ sp,
                                              const float* __restrict__ rp,
                                              const int*   __restrict__ inputs,
                                              const int*   __restrict__ sci,
                                              const int*   __restrict__ pc) {
    int b = blockIdx.x;
    if (b < 512) {
        // --- input rows: linear mantissas (rowmax=1) + log2 scale ---
        int w    = b * 8 + (threadIdx.x >> 5);
        int lane = threadIdx.x & 31;
        const float* row = ip + w * cC;
        float v[8];
        float tot = 0.f, mx = 0.f;
#pragma unroll
        for (int i = 0; i < 8; i++) {
            v[i] = row[lane + i * 32] + EPSF;
            tot += v[i];
            mx = fmaxf(mx, v[i]);
        }
#pragma unroll
        for (int o = 16; o; o >>= 1) {
            tot += __shfl_xor_sync(FULLM, tot, o);
            mx = fmaxf(mx, __shfl_xor_sync(FULLM, mx, o));
        }
        float inv = 1.f / mx;
#pragma unroll
        for (int i = 0; i < 8; i++)
            d_lwlin[w * cC + lane + i * 32] = __float2half_rn(v[i] * inv);
        if (lane == 0) d_eIn[w] = lg2(mx / tot);    // true = mant * 2^e
    } else if (b < 576) {
        // --- fused tables: one thread per (l,n): {c0*cBu4, c1*cBu4, W} ---
        int r = (b - 512) * 256 + threadIdx.x;
        int l = r / cN;
        const float* spr  = sp  + r * cF;
        const int*   scir = sci + r * cF;
        const int2*  pcl  = reinterpret_cast<const int2*>(pc) + l * cE;
        float w[cF];
        float tot = 0.f;
#pragma unroll
        for (int f = 0; f < cF; f++) { w[f] = spr[f] + EPSF; tot += w[f]; }
        float inv = 1.f / tot;
        int4* dst = d_fw + r * cF;
#pragma unroll
        for (int f = 0; f < cF; f++) {
            int2 c = pcl[scir[f]];
            dst[f] = make_int4(c.x * cBu4, c.y * cBu4, __float_as_int(w[f] * inv), 0);
        }
    } else if (b == 576) {
        // --- root params: linear normalize over N=4096 ---
        __shared__ float red[256];
        int t = threadIdx.x;
        float v[16];
        float s = 0.f;
#pragma unroll
        for (int i = 0; i < 16; i++) {
            v[i] = rp[t + i * 256] + EPSF;
            s += v[i];
        }
        red[t] = s;
        __syncthreads();
        for (int o = 128; o; o >>= 1) {
            if (t < o) red[t] += red[t + o];
            __syncthreads();
        }
        float inv = 1.f / red[0];
#pragma unroll
        for (int i = 0; i < 16; i++) d_R[t + i * 256] = v[i] * inv;
    } else {
        // --- transpose inputs (B,V) -> xT (V,B) ---
        int id = (b - 577) * 256 + threadIdx.x;
        for (int i = id; i < cV * cB; i += 64 * 256) {
            int bb = i >> 7;
            int vv = i & 127;
            d_xT[vv * cB + bb] = inputs[i];
        }
    }
}

// ==================================================================
// grid barrier (all GRID blocks resident).
// ==================================================================
__device__ __forceinline__ void grid_barrier() {
    __syncthreads();
    if (threadIdx.x == 0) {
        __threadfence();
        unsigned gen = d_bar_gen;
        unsigned t   = atomicAdd(&d_bar_count, 1u);
        if (t == GRID - 1) {
            d_bar_count = 0;
            __threadfence();
            d_bar_gen = gen + 1;
        } else {
            while (d_bar_gen == gen) { __nanosleep(64); }
        }
        __threadfence();
    }
    __syncthreads();
}

// ==================================================================
// PERSISTENT kernel — fp16 linear mantissa layers, per-(row,half) scales.
// Phase 0: block per (v, k-half); input table staged in SMEM; coalesced.
// Layers: task = warp per (n, row-half), EXACTLY 2 tasks per warp.
// ==================================================================
__global__ void __launch_bounds__(NT, BPSM) k_persist(float* __restrict__ out) {
    __shared__ __align__(16) char s_raw[2 * NT * 16];   // 16 KB, dual purpose
    float4* s_m = reinterpret_cast<float4*>(s_raw);
    float4* s_s = s_m + NT;
    const int t    = threadIdx.x;
    const int lane = t & 31;
    const int wid  = (blockIdx.x * NT + t) >> 5;   // global warp id

    // ---------- phase 0: SMEM-staged input gather -> d_nmA ----------
    {
        __half* s_lw = reinterpret_cast<__half*>(s_raw);   // 16 rows x 256 = 8 KB
        int v  = blockIdx.x >> 1;                 // 0..127
        int ks = (blockIdx.x & 1) << 4;           // 0 or 16
        // stage 16 k-rows of the fp16 table, coalesced (512 x 16B)
        reinterpret_cast<float4*>(s_lw)[t] =
            reinterpret_cast<const float4*>(d_lwlin + (v * cK + ks) * cC)[t];
        // layer-0 scales
        int gid = blockIdx.x * NT + t;
        if (gid < cN * 2) d_e0[gid] = d_eIn[gid >> 1];
        __syncthreads();
        int x = d_xT[v * cB + t];                 // thread t <-> batch b = t
#pragma unroll
        for (int k = 0; k < 16; k++)
            d_nmA[(v * cK + ks + k) * cB + t] = s_lw[k * cC + x];
        __syncthreads();
    }
    grid_barrier();

    // ---------- 4 fused linear layers ----------
    __half* nm_src = d_nmA;
    __half* nm_dst = d_nmB;
    const float* esrc = d_e0;
    for (int l = 0; l < cL; l++) {
        float* edst = (l & 1) ? d_eB : d_eA;
        const int4*  fwl = d_fw + l * cN * cF;
        const uint4* nmS = reinterpret_cast<const uint4*>(nm_src);

        for (int task = wid; task < cN * 2; task += NWARP) {
            int n = task >> 1;
            int h = task & 1;
            int g = (h << 5) + lane;           // uint4 index in row
            // lane f (mirrored at f+16) owns table entry f
            int4 pm = __ldg(fwl + n * cF + (lane & 15));
            // per-(row,half) scale: idx = row*2+h = (pm.x>>5)+h
            float g_my = __ldg(esrc + (pm.x >> 5) + h) + __ldg(esrc + (pm.y >> 5) + h);
            float G = g_my;
#pragma unroll
            for (int o = 1; o < 16; o <<= 1)
                G = fmaxf(G, __shfl_xor_sync(FULLM, G, o));
            float coef_my = __int_as_float(pm.z) * ex2(g_my - G);

            // depth-2 pipelined gathers (16B/lane covers 8 batch elems)
            uint4 aA = nmS[__shfl_sync(FULLM, pm.x, 0) + g];
            uint4 bA = nmS[__shfl_sync(FULLM, pm.y, 0) + g];
            uint4 aB = nmS[__shfl_sync(FULLM, pm.x, 1) + g];
            uint4 bB = nmS[__shfl_sync(FULLM, pm.y, 1) + g];

            float acc[8];
#pragma unroll
            for (int j = 0; j < 8; j++) acc[j] = 0.f;

#pragma unroll
            for (int f = 0; f < cF; f++) {
                float cf = __shfl_sync(FULLM, coef_my, f);
                uint4 a = aA, b = bA;
                aA = aB; bA = bB;
                if (f + 2 < cF) {
                    aB = nmS[__shfl_sync(FULLM, pm.x, f + 2) + g];
                    bB = nmS[__shfl_sync(FULLM, pm.y, f + 2) + g];
                }
                float2 p0 = __half22float2(__hmul2(u2h2(a.x), u2h2(b.x)));
                float2 p1 = __half22float2(__hmul2(u2h2(a.y), u2h2(b.y)));
                float2 p2 = __half22float2(__hmul2(u2h2(a.z), u2h2(b.z)));
                float2 p3 = __half22float2(__hmul2(u2h2(a.w), u2h2(b.w)));
                acc[0] += cf * p0.x; acc[1] += cf * p0.y;
                acc[2] += cf * p1.x; acc[3] += cf * p1.y;
                acc[4] += cf * p2.x; acc[5] += cf * p2.y;
                acc[6] += cf * p3.x; acc[7] += cf * p3.y;
            }

            if (l < cL - 1) {
                // half-row renormalize: qmax -> 1, fold into e_out
                float qm = acc[0];
#pragma unroll
                for (int j = 1; j < 8; j++) qm = fmaxf(qm, acc[j]);
#pragma unroll
                for (int o = 16; o; o >>= 1)
                    qm = fmaxf(qm, __shfl_xor_sync(FULLM, qm, o));
                float ri = rcp(qm);
                uint4 o4;
                o4.x = h2u(__floats2half2_rn(acc[0] * ri, acc[1] * ri));
                o4.y = h2u(__floats2half2_rn(acc[2] * ri, acc[3] * ri));
                o4.z = h2u(__floats2half2_rn(acc[4] * ri, acc[5] * ri));
                o4.w = h2u(__floats2half2_rn(acc[6] * ri, acc[7] * ri));
                __stcg(reinterpret_cast<uint4*>(nm_dst) + n * cBu4 + g, o4);
                if (lane == 0) edst[n * 2 + h] = G + lg2(qm);
            } else {
                // final layer: emit fp32 log2 values for the root reduction
                float4 w0, w1;
                w0.x = G + lg2(acc[0]); w0.y = G + lg2(acc[1]);
                w0.z = G + lg2(acc[2]); w0.w = G + lg2(acc[3]);
                w1.x = G + lg2(acc[4]); w1.y = G + lg2(acc[5]);
                w1.z = G + lg2(acc[6]); w1.w = G + lg2(acc[7]);
                float4* fd = reinterpret_cast<float4*>(d_fin) + n * cB4 + g * 2;
                __stcg(fd, w0);
                __stcg(fd + 1, w1);
            }
        }
        grid_barrier();

        __half* tmp = nm_src; nm_src = nm_dst; nm_dst = tmp;
        esrc = edst;
    }

    // ---------- root: out[b] = ln2 * (m + lg2(sum_n R_n 2^(x_nb - m))) ----------
    if (blockIdx.x < cB4) {
        const int g = blockIdx.x;              // float4 batch group
        const float4* nmp = reinterpret_cast<const float4*>(d_fin);

        float R0 = __ldg(d_R + t);
        float4 m = nmp[t * cB4 + g];
        float4 s = make_float4(R0, R0, R0, R0);
#pragma unroll
        for (int k = 1; k < cN / NT; k++) {
            int   n = t + k * NT;
            float R = __ldg(d_R + n);
            float4 x = nmp[n * cB4 + g];
            s.x += R * ex2(x.x - m.x);
            s.y += R * ex2(x.y - m.y);
            s.z += R * ex2(x.z - m.z);
            s.w += R * ex2(x.w - m.w);
        }
        s_m[t] = m; s_s[t] = s;
        __syncthreads();
        for (int o = NT / 2; o; o >>= 1) {
            if (t < o) {
                float4 m1 = s_m[t], m2 = s_m[t + o];
                float4 s1 = s_s[t], s2 = s_s[t + o];
                float4 mm, ss;
                mm.x = fmaxf(m1.x, m2.x);
                mm.y = fmaxf(m1.y, m2.y);
                mm.z = fmaxf(m1.z, m2.z);
                mm.w = fmaxf(m1.w, m2.w);
                ss.x = s1.x * ex2(m1.x - mm.x) + s2.x * ex2(m2.x - mm.x);
                ss.y = s1.y * ex2(m1.y - mm.y) + s2.y * ex2(m2.y - mm.y);
                ss.z = s1.z * ex2(m1.z - mm.z) + s2.z * ex2(m2.z - mm.z);
                ss.w = s1.w * ex2(m1.w - mm.w) + s2.w * ex2(m2.w - mm.w);
                s_m[t] = mm; s_s[t] = ss;
            }
            __syncthreads();
        }
        if (t == 0) {
            float4 m0 = s_m[0], s0 = s_s[0];
            out[g * 4 + 0] = (m0.x + lg2(s0.x)) * LN2F;
            out[g * 4 + 1] = (m0.y + lg2(s0.y)) * LN2F;
            out[g * 4 + 2] = (m0.z + lg2(s0.z)) * LN2F;
            out[g * 4 + 3] = (m0.w + lg2(s0.w)) * LN2F;
        }
    }
}

// ==================================================================
extern "C" void kernel_launch(void* const* d_in, const int* in_sizes, int n_in,
                              void* d_out, int out_size) {
    const int*   inputs = (const int*)d_in[0];    // (B, V)
    const int*   pc     = (const int*)d_in[1];    // (L, E, 2)
    const int*   sci    = (const int*)d_in[2];    // (L, N, F)
    const float* ip     = (const float*)d_in[3];  // (V, K, C)
    const float* sp     = (const float*)d_in[4];  // (L, N, F)
    const float* rp     = (const float*)d_in[5];  // (N,)
    float* out = (float*)d_out;                   // (B,)

    k_prep<<<641, 256>>>(ip, sp, rp, inputs, sci, pc);
    k_persist<<<GRID, NT>>>(out);
}